// round 16
// baseline (speedup 1.0000x reference)
#include <cuda_runtime.h>
#include <math.h>
#include <stdint.h>

#define NGRAPH 64
#define NPG    256
#define NNODE  (NGRAPH * NPG)   // 16384
#define KNN    100
#define FIN    5
#define H      128
#define H2     768
#define SLICE  64               // features per agg2_h block (2 blocks/graph)
#define TAG_NPB 32
#define TAG_STRIDE 36           // 144B rows: 16B-aligned for LDS.128
#define DRPB   2                // rows per dense block -> 6*32 = 192 blocks
#define DQ     8                // split-K segments per dense block

// ---------------- scratch (static device globals; no allocation) ------------
__device__ int   g_nbr[NNODE * KNN];
__device__ float g_a1[NNODE * FIN];
__device__ float g_a2[NNODE * FIN];
__device__ float g_hA[NNODE * H];
__device__ float g_hB[NNODE * H];
__device__ float g_t1[NNODE * H];
__device__ float g_t2[NNODE * H];
__device__ float g_G [NGRAPH * H2];
__device__ float g_G2[NGRAPH * H2];

__device__ __forceinline__ float leaky(float v) { return v > 0.0f ? v : 0.01f * v; }

// ---------------- 1. kNN: bitonic sort of packed u64 ------------------------
__global__ void knn_kernel(const float* __restrict__ x) {
    int i = blockIdx.x;            // node id
    int base = (i / NPG) * NPG;    // graph base
    int t = threadIdx.x;           // 0..255 candidate

    __shared__ float xi[FIN];
    __shared__ unsigned long long key[NPG];

    if (t < FIN) xi[t] = x[i * FIN + t];
    __syncthreads();

    float d = 0.0f;
#pragma unroll
    for (int f = 0; f < FIN; f++) {
        float df = x[(base + t) * FIN + f] - xi[f];
        d += df * df;
    }
    if (base + t == i) d = 1e30f;   // exclude self
    key[t] = ((unsigned long long)__float_as_uint(d) << 32) | (unsigned)t;
    __syncthreads();

    // Barrier BEFORE each phase: j>=16 -> syncthreads (covers this phase's
    // read distance and the previous phase's write distance), else syncwarp.
    for (int k = 2; k <= NPG; k <<= 1) {
        for (int j = k >> 1; j > 0; j >>= 1) {
            if (j >= 16) __syncthreads();
            else         __syncwarp();
            int ixj = t ^ j;
            if (ixj > t) {
                unsigned long long a = key[t], b = key[ixj];
                bool up = ((t & k) == 0);
                if (up ? (a > b) : (a < b)) {
                    key[t] = b; key[ixj] = a;
                }
            }
        }
    }
    __syncthreads();
    if (t < KNN) g_nbr[i * KNN + t] = base + (int)(key[t] & 0xffffffffu);
}

// ---------------- 2a. fused 2-hop aggregation, F=5 (one block per graph) ----
__global__ void agg2_fin_kernel(const float* __restrict__ x,
                                float* __restrict__ a1g, float* __restrict__ a2g) {
    extern __shared__ __align__(16) char smraw[];
    int*   NB = (int*)smraw;                 // [NPG][101] local neighbor ids
    float* X  = (float*)(NB + NPG * 101);    // [NPG][FIN]
    float* A1 = X + NPG * FIN;               // [NPG][FIN]
    int g = blockIdx.x, base = g * NPG, t = threadIdx.x;

    for (int e = t; e < NPG * FIN; e += 256) X[e] = x[base * FIN + e];
    for (int e = t; e < NPG * KNN; e += 256) {
        int n = e / KNN, k = e - n * KNN;
        NB[n * 101 + k] = g_nbr[base * KNN + e] - base;
    }
    __syncthreads();

    const int* nb = NB + t * 101;
    float acc[FIN];
#pragma unroll
    for (int f = 0; f < FIN; f++) acc[f] = 0.0f;
    for (int k = 0; k < KNN; k++) {
        int j = nb[k];
#pragma unroll
        for (int f = 0; f < FIN; f++) acc[f] += X[j * FIN + f];
    }
#pragma unroll
    for (int f = 0; f < FIN; f++) {
        float v = 0.01f * acc[f];
        A1[t * FIN + f] = v;
        a1g[(base + t) * FIN + f] = v;
    }
    __syncthreads();

#pragma unroll
    for (int f = 0; f < FIN; f++) acc[f] = 0.0f;
    for (int k = 0; k < KNN; k++) {
        int j = nb[k];
#pragma unroll
        for (int f = 0; f < FIN; f++) acc[f] += A1[j * FIN + f];
    }
#pragma unroll
    for (int f = 0; f < FIN; f++) a2g[(base + t) * FIN + f] = 0.01f * acc[f];
}

// ---------------- 2b. fused 2-hop aggregation, F=128 (2 blocks/graph) -------
// 1024 threads; byte-packed index broadcast + packed f32x2 tree adds.
__global__ __launch_bounds__(1024) void agg2_h_kernel(
    const float* __restrict__ h, float* __restrict__ a1g, float* __restrict__ a2g) {
    extern __shared__ __align__(16) float sm[];
    uint64_t* Xu  = (uint64_t*)sm;                    // [NPG][32] float2-as-u64
    uint64_t* A1u = (uint64_t*)(sm + NPG * SLICE);
    int g = blockIdx.x >> 1;
    int s = blockIdx.x & 1;
    int base = g * NPG;
    int fofs = s * SLICE;
    int t = threadIdx.x, lane = t & 31, w = t >> 5;  // 32 warps

    for (int e = t; e < NPG * SLICE / 4; e += 1024) {
        int n  = e / (SLICE / 4);
        int f4 = e - n * (SLICE / 4);
        float4 v = *(const float4*)&h[(base + n) * H + fofs + f4 * 4];
        ((float4*)sm)[n * (SLICE / 4) + f4] = v;
    }
    __syncthreads();

    for (int n = w; n < NPG; n += 32) {
        unsigned pw = 0;
        if (lane < KNN / 4) {
            int4 v = ((const int4*)&g_nbr[(base + n) * KNN])[lane];
            pw = (unsigned)(v.x - base) | ((unsigned)(v.y - base) << 8)
               | ((unsigned)(v.z - base) << 16) | ((unsigned)(v.w - base) << 24);
        }
        uint64_t sacc = 0;  // packed (0.0f, 0.0f)
#pragma unroll 5
        for (int k4 = 0; k4 < KNN / 4; k4++) {
            unsigned p = __shfl_sync(0xffffffffu, pw, k4);
            uint64_t v0 = Xu[(p & 255u) * 32 + lane];
            uint64_t v1 = Xu[((p >> 8) & 255u) * 32 + lane];
            uint64_t v2 = Xu[((p >> 16) & 255u) * 32 + lane];
            uint64_t v3 = Xu[(p >> 24) * 32 + lane];
            uint64_t t0, t1;
            asm("add.rn.f32x2 %0, %1, %2;" : "=l"(t0) : "l"(v0), "l"(v1));
            asm("add.rn.f32x2 %0, %1, %2;" : "=l"(t1) : "l"(v2), "l"(v3));
            asm("add.rn.f32x2 %0, %0, %1;" : "+l"(t0) : "l"(t1));
            asm("add.rn.f32x2 %0, %0, %1;" : "+l"(sacc) : "l"(t0));
        }
        float sx, sy;
        asm("mov.b64 {%0, %1}, %2;" : "=f"(sx), "=f"(sy) : "l"(sacc));
        float2 o; o.x = 0.01f * sx; o.y = 0.01f * sy;
        uint64_t ov; asm("mov.b64 %0, {%1, %2};" : "=l"(ov) : "f"(o.x), "f"(o.y));
        A1u[n * 32 + lane] = ov;
        *(float2*)&a1g[(base + n) * H + fofs + 2 * lane] = o;
    }
    __syncthreads();

    for (int n = w; n < NPG; n += 32) {
        unsigned pw = 0;
        if (lane < KNN / 4) {
            int4 v = ((const int4*)&g_nbr[(base + n) * KNN])[lane];
            pw = (unsigned)(v.x - base) | ((unsigned)(v.y - base) << 8)
               | ((unsigned)(v.z - base) << 16) | ((unsigned)(v.w - base) << 24);
        }
        uint64_t sacc = 0;
#pragma unroll 5
        for (int k4 = 0; k4 < KNN / 4; k4++) {
            unsigned p = __shfl_sync(0xffffffffu, pw, k4);
            uint64_t v0 = A1u[(p & 255u) * 32 + lane];
            uint64_t v1 = A1u[((p >> 8) & 255u) * 32 + lane];
            uint64_t v2 = A1u[((p >> 16) & 255u) * 32 + lane];
            uint64_t v3 = A1u[(p >> 24) * 32 + lane];
            uint64_t t0, t1;
            asm("add.rn.f32x2 %0, %1, %2;" : "=l"(t0) : "l"(v0), "l"(v1));
            asm("add.rn.f32x2 %0, %1, %2;" : "=l"(t1) : "l"(v2), "l"(v3));
            asm("add.rn.f32x2 %0, %0, %1;" : "+l"(t0) : "l"(t1));
            asm("add.rn.f32x2 %0, %0, %1;" : "+l"(sacc) : "l"(t0));
        }
        float sx, sy;
        asm("mov.b64 {%0, %1}, %2;" : "=f"(sx), "=f"(sy) : "l"(sacc));
        float2 o; o.x = 0.01f * sx; o.y = 0.01f * sy;
        *(float2*)&a2g[(base + n) * H + fofs + 2 * lane] = o;
    }
}

// ---------------- 3a. TAGConv combine F=5 -----------------------------------
template <int F, int NPB>
__global__ void tag_kernel(const float* __restrict__ x0, const float* __restrict__ a1,
                           const float* __restrict__ a2, const float* __restrict__ W,
                           const float* __restrict__ bias, float* __restrict__ out) {
    __shared__ float s0[NPB * F], s1[NPB * F], s2[NPB * F];
    int n0 = blockIdx.x * NPB;
    int t = threadIdx.x;  // output channel

    for (int e = t; e < NPB * F; e += 128) {
        s0[e] = x0[n0 * F + e];
        s1[e] = a1[n0 * F + e];
        s2[e] = a2[n0 * F + e];
    }
    __syncthreads();

    float acc[NPB];
#pragma unroll
    for (int n = 0; n < NPB; n++) acc[n] = bias[t];

    for (int j = 0; j < F; j++) {
        float w0 = W[(0 * F + j) * H + t];
        float w1 = W[(1 * F + j) * H + t];
        float w2 = W[(2 * F + j) * H + t];
#pragma unroll
        for (int n = 0; n < NPB; n++)
            acc[n] += s0[n * F + j] * w0 + s1[n * F + j] * w1 + s2[n * F + j] * w2;
    }
#pragma unroll
    for (int n = 0; n < NPB; n++)
        out[(n0 + n) * H + t] = leaky(acc[n]);
}

// ---------------- 3b. TAGConv combine F=128, packed f32x2 + LDS.128 ---------
__global__ __launch_bounds__(128) void tagh_kernel(
    const float* __restrict__ x0, const float* __restrict__ a1,
    const float* __restrict__ a2, const float* __restrict__ W,
    const float* __restrict__ bias, float* __restrict__ out) {
    extern __shared__ __align__(16) float sp[];  // 3 * H * TAG_STRIDE floats
    int n0 = blockIdx.x * TAG_NPB;
    int t = threadIdx.x;

    {
        const float* srcs[3] = {x0 + n0 * H, a1 + n0 * H, a2 + n0 * H};
#pragma unroll
        for (int kk = 0; kk < 3; kk++) {
            float* dst = sp + kk * H * TAG_STRIDE;
            const float* src = srcs[kk];
            for (int e = t; e < TAG_NPB * H; e += 128) {
                int n = e >> 7, j = e & 127;
                dst[j * TAG_STRIDE + n] = src[e];  // transposed: [j][node]
            }
        }
    }
    __syncthreads();

    float bs = bias[t];
    uint64_t acc[TAG_NPB / 2];
    uint64_t bp;
    asm("mov.b64 %0, {%1, %1};" : "=l"(bp) : "f"(bs));
#pragma unroll
    for (int p = 0; p < TAG_NPB / 2; p++) acc[p] = bp;

    const float* sp0 = sp;
    const float* sp1 = sp + H * TAG_STRIDE;
    const float* sp2 = sp + 2 * H * TAG_STRIDE;
    for (int j = 0; j < H; j++) {
        float w0 = W[j * H + t];
        float w1 = W[(H + j) * H + t];
        float w2 = W[(2 * H + j) * H + t];
        uint64_t w0p, w1p, w2p;
        asm("mov.b64 %0, {%1, %1};" : "=l"(w0p) : "f"(w0));
        asm("mov.b64 %0, {%1, %1};" : "=l"(w1p) : "f"(w1));
        asm("mov.b64 %0, {%1, %1};" : "=l"(w2p) : "f"(w2));
        const ulonglong2* v0 = (const ulonglong2*)(sp0 + j * TAG_STRIDE);
        const ulonglong2* v1 = (const ulonglong2*)(sp1 + j * TAG_STRIDE);
        const ulonglong2* v2 = (const ulonglong2*)(sp2 + j * TAG_STRIDE);
#pragma unroll
        for (int q = 0; q < TAG_NPB / 4; q++) {
            ulonglong2 a0 = v0[q];
            ulonglong2 a1v = v1[q];
            ulonglong2 a2v = v2[q];
            asm("fma.rn.f32x2 %0, %1, %2, %0;" : "+l"(acc[2 * q])     : "l"(a0.x),  "l"(w0p));
            asm("fma.rn.f32x2 %0, %1, %2, %0;" : "+l"(acc[2 * q + 1]) : "l"(a0.y),  "l"(w0p));
            asm("fma.rn.f32x2 %0, %1, %2, %0;" : "+l"(acc[2 * q])     : "l"(a1v.x), "l"(w1p));
            asm("fma.rn.f32x2 %0, %1, %2, %0;" : "+l"(acc[2 * q + 1]) : "l"(a1v.y), "l"(w1p));
            asm("fma.rn.f32x2 %0, %1, %2, %0;" : "+l"(acc[2 * q])     : "l"(a2v.x), "l"(w2p));
            asm("fma.rn.f32x2 %0, %1, %2, %0;" : "+l"(acc[2 * q + 1]) : "l"(a2v.y), "l"(w2p));
        }
    }
#pragma unroll
    for (int p = 0; p < TAG_NPB / 2; p++) {
        float lo, hi;
        asm("mov.b64 {%0, %1}, %2;" : "=f"(lo), "=f"(hi) : "l"(acc[p]));
        out[(n0 + 2 * p) * H + t]     = leaky(lo);
        out[(n0 + 2 * p + 1) * H + t] = leaky(hi);
    }
}

// ---------------- 4. mean+max pool per graph (1024 threads) -----------------
__global__ void pool_kernel(const float* __restrict__ h, int col, float* __restrict__ G) {
    int b = blockIdx.x;
    int f = threadIdx.x & 127;        // feature
    int strip = threadIdx.x >> 7;     // 0..7
    float s = 0.0f, m = -1e30f;
    for (int n = strip; n < NPG; n += 8) {
        float v = h[(b * NPG + n) * H + f];
        s += v;
        m = fmaxf(m, v);
    }
    __shared__ float ssum[1024], smax[1024];
    ssum[threadIdx.x] = s;
    smax[threadIdx.x] = m;
    __syncthreads();
    if (strip == 0) {
#pragma unroll
        for (int o = 1; o < 8; o++) {
            s += ssum[o * 128 + f];
            m = fmaxf(m, smax[o * 128 + f]);
        }
        G[b * H2 + col + f]     = s * (1.0f / NPG);
        G[b * H2 + col + H + f] = m;
    }
}

// ---------------- 5. batchnorm over batch dim -------------------------------
__global__ void bn_kernel(float* __restrict__ G, const float* __restrict__ gamma,
                          const float* __restrict__ beta) {
    int c = blockIdx.x * blockDim.x + threadIdx.x;
    if (c >= H2) return;
    float s = 0.0f;
    for (int b = 0; b < NGRAPH; b++) s += G[b * H2 + c];
    float mu = s * (1.0f / NGRAPH);
    float v = 0.0f;
    for (int b = 0; b < NGRAPH; b++) { float d = G[b * H2 + c] - mu; v += d * d; }
    v *= (1.0f / NGRAPH);
    float sc = rsqrtf(v + 1e-5f) * gamma[c];
    float bt = beta[c];
    for (int b = 0; b < NGRAPH; b++)
        G[b * H2 + c] = (G[b * H2 + c] - mu) * sc + bt;
}

// ---------------- 6. dense 768x768 + leaky: 192 blk x 1024 thr, split-K x8 --
__global__ __launch_bounds__(1024) void dense_kernel(
    const float* __restrict__ in, const float* __restrict__ W,
    const float* __restrict__ bias, float* __restrict__ out) {
    __shared__ float s[DRPB * H2];                 // 6 KB
    __shared__ float red[(DQ - 1) * DRPB * 128];   // 7 KB
    int lane = threadIdx.x & 127;
    int q = threadIdx.x >> 7;               // 0..7 = k-segment
    int colblk = blockIdx.x % (H2 / 128);   // 0..5
    int rowblk = blockIdx.x / (H2 / 128);   // 0..31
    int col = colblk * 128 + lane;
    int r0 = rowblk * DRPB;

    for (int e = threadIdx.x; e < DRPB * H2; e += 1024) s[e] = in[r0 * H2 + e];
    __syncthreads();

    const int seg = H2 / DQ;                // 96
    int j0 = q * seg;
    int jend = j0 + seg;

    float a0 = 0.0f, a1 = 0.0f;
    float w0 = W[(j0 + 0) * H2 + col];
    float w1 = W[(j0 + 1) * H2 + col];
    float w2 = W[(j0 + 2) * H2 + col];
    float w3 = W[(j0 + 3) * H2 + col];
    for (int j = j0; j < jend; j += 4) {
        float nw0 = 0.0f, nw1 = 0.0f, nw2 = 0.0f, nw3 = 0.0f;
        if (j + 4 < jend) {                 // predicated preload of next group
            nw0 = W[(j + 4) * H2 + col];
            nw1 = W[(j + 5) * H2 + col];
            nw2 = W[(j + 6) * H2 + col];
            nw3 = W[(j + 7) * H2 + col];
        }
        a0 += s[j + 0] * w0; a1 += s[H2 + j + 0] * w0;
        a0 += s[j + 1] * w1; a1 += s[H2 + j + 1] * w1;
        a0 += s[j + 2] * w2; a1 += s[H2 + j + 2] * w2;
        a0 += s[j + 3] * w3; a1 += s[H2 + j + 3] * w3;
        w0 = nw0; w1 = nw1; w2 = nw2; w3 = nw3;
    }
    if (q) {
        red[((q - 1) * DRPB + 0) * 128 + lane] = a0;
        red[((q - 1) * DRPB + 1) * 128 + lane] = a1;
    }
    __syncthreads();
    if (!q) {
        float bs = bias[col];
#pragma unroll
        for (int seg7 = 0; seg7 < DQ - 1; seg7++) {
            a0 += red[(seg7 * DRPB + 0) * 128 + lane];
            a1 += red[(seg7 * DRPB + 1) * 128 + lane];
        }
        out[(r0 + 0) * H2 + col] = leaky(a0 + bs);
        out[(r0 + 1) * H2 + col] = leaky(a1 + bs);
    }
}

// ---------------- 7. output projection 768 -> 1 -----------------------------
__global__ void final_kernel(const float* __restrict__ G, const float* __restrict__ w,
                             const float* __restrict__ b, float* __restrict__ out) {
    int row = blockIdx.x, t = threadIdx.x;
    float s = 0.0f;
    for (int j = t; j < H2; j += 128) s += G[row * H2 + j] * w[j];
    __shared__ float red[128];
    red[t] = s;
    __syncthreads();
    for (int o = 64; o > 0; o >>= 1) {
        if (t < o) red[t] += red[t + o];
        __syncthreads();
    }
    if (t == 0) out[row] = red[0] + b[0];
}

// ---------------- host launcher ---------------------------------------------
extern "C" void kernel_launch(void* const* d_in, const int* in_sizes, int n_in,
                              void* d_out, int out_size) {
    const float* x       = (const float*)d_in[0];
    const float* conv1_w = (const float*)d_in[2];
    const float* conv1_b = (const float*)d_in[3];
    const float* conv2_w = (const float*)d_in[4];
    const float* conv2_b = (const float*)d_in[5];
    const float* conv3_w = (const float*)d_in[6];
    const float* conv3_b = (const float*)d_in[7];
    const float* bn_g    = (const float*)d_in[8];
    const float* bn_b    = (const float*)d_in[9];
    const float* lin_w   = (const float*)d_in[10];
    const float* lin_b   = (const float*)d_in[11];
    const float* out_w   = (const float*)d_in[12];
    const float* out_b   = (const float*)d_in[13];
    float* out = (float*)d_out;

    float *a1, *a2, *hA, *hB, *t1, *t2, *G, *G2;
    cudaGetSymbolAddress((void**)&a1, g_a1);
    cudaGetSymbolAddress((void**)&a2, g_a2);
    cudaGetSymbolAddress((void**)&hA, g_hA);
    cudaGetSymbolAddress((void**)&hB, g_hB);
    cudaGetSymbolAddress((void**)&t1, g_t1);
    cudaGetSymbolAddress((void**)&t2, g_t2);
    cudaGetSymbolAddress((void**)&G,  g_G);
    cudaGetSymbolAddress((void**)&G2, g_G2);

    const int smemFin = NPG * 101 * 4 + 2 * NPG * FIN * 4;      // 113664
    const int smemH   = 2 * NPG * SLICE * 4;                    // 131072
    const int smemTag = 3 * H * TAG_STRIDE * 4;                 // 55296
    cudaFuncSetAttribute(agg2_fin_kernel, cudaFuncAttributeMaxDynamicSharedMemorySize, smemFin);
    cudaFuncSetAttribute(agg2_h_kernel,   cudaFuncAttributeMaxDynamicSharedMemorySize, smemH);
    cudaFuncSetAttribute(tagh_kernel,     cudaFuncAttributeMaxDynamicSharedMemorySize, smemTag);

    const int dgrid = (H2 / 128) * (NGRAPH / DRPB);   // 6 * 32 = 192

    // launch index:                                                          //
    knn_kernel<<<NNODE, 256>>>(x);                                            // 0
    agg2_fin_kernel<<<NGRAPH, 256, smemFin>>>(x, a1, a2);                     // 1
    tag_kernel<FIN, 32><<<NNODE / 32, 128>>>(x, a1, a2, conv1_w, conv1_b, hA);// 2
    // PROBE: idempotent knn duplicate at the profiled slot (writes identical
    // g_nbr values; zero correctness impact). Measures knn's true duration.
    knn_kernel<<<NNODE, 256>>>(x);                                            // 3 <- profiled
    agg2_h_kernel<<<NGRAPH * 2, 1024, smemH>>>(hA, t1, t2);                   // 4
    pool_kernel<<<NGRAPH, 1024>>>(hA, 0, G);                                  // 5
    tagh_kernel<<<NNODE / TAG_NPB, 128, smemTag>>>(hA, t1, t2, conv2_w, conv2_b, hB); // 6
    agg2_h_kernel<<<NGRAPH * 2, 1024, smemH>>>(hB, t1, t2);                   // 7
    pool_kernel<<<NGRAPH, 1024>>>(hB, 2 * H, G);                              // 8
    tagh_kernel<<<NNODE / TAG_NPB, 128, smemTag>>>(hB, t1, t2, conv3_w, conv3_b, hA); // 9
    pool_kernel<<<NGRAPH, 1024>>>(hA, 4 * H, G);                              // 10

    bn_kernel<<<6, 128>>>(G, bn_g, bn_b);

    dense_kernel<<<dgrid, 1024>>>(G,  lin_w + 0 * H2 * H2, lin_b + 0 * H2, G2);
    dense_kernel<<<dgrid, 1024>>>(G2, lin_w + 1 * H2 * H2, lin_b + 1 * H2, G);
    dense_kernel<<<dgrid, 1024>>>(G,  lin_w + 2 * H2 * H2, lin_b + 2 * H2, G2);
    dense_kernel<<<dgrid, 1024>>>(G2, lin_w + 3 * H2 * H2, lin_b + 3 * H2, G);
    dense_kernel<<<dgrid, 1024>>>(G,  lin_w + 4 * H2 * H2, lin_b + 4 * H2, G2);

    final_kernel<<<NGRAPH, 128>>>(G2, out_w, out_b, out);
}

// round 17
// speedup vs baseline: 1.3626x; 1.3626x over previous
#include <cuda_runtime.h>
#include <math.h>
#include <stdint.h>

#define NGRAPH 64
#define NPG    256
#define NNODE  (NGRAPH * NPG)   // 16384
#define KNN    100
#define FIN    5
#define H      128
#define H2     768
#define SLICE  64               // features per agg2_h block (2 blocks/graph)
#define TAG_NPB 32
#define TAG_STRIDE 36           // 144B rows: 16B-aligned for LDS.128
#define DRPB   2                // rows per dense block -> 6*32 = 192 blocks
#define DQ     8                // split-K segments per dense block

// ---------------- scratch (static device globals; no allocation) ------------
__device__ int   g_nbr[NNODE * KNN];
__device__ float g_a1[NNODE * FIN];
__device__ float g_a2[NNODE * FIN];
__device__ float g_hA[NNODE * H];
__device__ float g_hB[NNODE * H];
__device__ float g_t1[NNODE * H];
__device__ float g_t2[NNODE * H];
__device__ float g_G [NGRAPH * H2];
__device__ float g_G2[NGRAPH * H2];

__device__ __forceinline__ float leaky(float v) { return v > 0.0f ? v : 0.01f * v; }

// ---------------- 1. kNN: register-resident bitonic sort --------------------
// R16 profile: smem-key version = 117.8us, L1=94% (port-bound on 36 phases of
// u64 round-trips). Keys now live in registers: 30/36 phases are intra-warp
// shfl_xor (no smem, no barriers); only the 6 j>=32 phases touch smem.
// Same compare network + keys -> bit-identical sorted order.
__global__ void knn_kernel(const float* __restrict__ x) {
    int i = blockIdx.x;            // node id
    int base = (i / NPG) * NPG;    // graph base
    int t = threadIdx.x;           // 0..255 candidate

    __shared__ float xi[FIN];
    __shared__ unsigned long long sm[NPG];

    if (t < FIN) xi[t] = x[i * FIN + t];
    __syncthreads();

    float d = 0.0f;
#pragma unroll
    for (int f = 0; f < FIN; f++) {
        float df = x[(base + t) * FIN + f] - xi[f];
        d += df * df;
    }
    if (base + t == i) d = 1e30f;   // exclude self
    // pack (d2, idx): d2 >= 0 so float bits are order-monotonic; ties -> lower idx
    unsigned long long key =
        ((unsigned long long)__float_as_uint(d) << 32) | (unsigned)t;

    for (int k = 2; k <= NPG; k <<= 1) {
        for (int j = k >> 1; j > 0; j >>= 1) {
            bool keep_min = ((t & k) == 0) ^ ((t & j) != 0);
            unsigned long long other;
            if (j >= 32) {
                __syncthreads();          // prior phase's reads complete
                sm[t] = key;
                __syncthreads();
                other = sm[t ^ j];
            } else {
                other = __shfl_xor_sync(0xffffffffu, key, j);
            }
            key = keep_min ? (key < other ? key : other)
                           : (key > other ? key : other);
        }
    }
    // ascending sort: thread t holds the t-th smallest
    if (t < KNN) g_nbr[i * KNN + t] = base + (int)(key & 0xffffffffu);
}

// ---------------- 2a. fused 2-hop aggregation, F=5 (one block per graph) ----
__global__ void agg2_fin_kernel(const float* __restrict__ x,
                                float* __restrict__ a1g, float* __restrict__ a2g) {
    extern __shared__ __align__(16) char smraw[];
    int*   NB = (int*)smraw;                 // [NPG][101] local neighbor ids
    float* X  = (float*)(NB + NPG * 101);    // [NPG][FIN]
    float* A1 = X + NPG * FIN;               // [NPG][FIN]
    int g = blockIdx.x, base = g * NPG, t = threadIdx.x;

    for (int e = t; e < NPG * FIN; e += 256) X[e] = x[base * FIN + e];
    for (int e = t; e < NPG * KNN; e += 256) {
        int n = e / KNN, k = e - n * KNN;
        NB[n * 101 + k] = g_nbr[base * KNN + e] - base;
    }
    __syncthreads();

    const int* nb = NB + t * 101;
    float acc[FIN];
#pragma unroll
    for (int f = 0; f < FIN; f++) acc[f] = 0.0f;
    for (int k = 0; k < KNN; k++) {
        int j = nb[k];
#pragma unroll
        for (int f = 0; f < FIN; f++) acc[f] += X[j * FIN + f];
    }
#pragma unroll
    for (int f = 0; f < FIN; f++) {
        float v = 0.01f * acc[f];
        A1[t * FIN + f] = v;
        a1g[(base + t) * FIN + f] = v;
    }
    __syncthreads();

#pragma unroll
    for (int f = 0; f < FIN; f++) acc[f] = 0.0f;
    for (int k = 0; k < KNN; k++) {
        int j = nb[k];
#pragma unroll
        for (int f = 0; f < FIN; f++) acc[f] += A1[j * FIN + f];
    }
#pragma unroll
    for (int f = 0; f < FIN; f++) a2g[(base + t) * FIN + f] = 0.01f * acc[f];
}

// ---------------- 2b. fused 2-hop aggregation, F=128 (2 blocks/graph) -------
// 1024 threads; byte-packed index broadcast + packed f32x2 tree adds.
__global__ __launch_bounds__(1024) void agg2_h_kernel(
    const float* __restrict__ h, float* __restrict__ a1g, float* __restrict__ a2g) {
    extern __shared__ __align__(16) float sm[];
    uint64_t* Xu  = (uint64_t*)sm;                    // [NPG][32] float2-as-u64
    uint64_t* A1u = (uint64_t*)(sm + NPG * SLICE);
    int g = blockIdx.x >> 1;
    int s = blockIdx.x & 1;
    int base = g * NPG;
    int fofs = s * SLICE;
    int t = threadIdx.x, lane = t & 31, w = t >> 5;  // 32 warps

    for (int e = t; e < NPG * SLICE / 4; e += 1024) {
        int n  = e / (SLICE / 4);
        int f4 = e - n * (SLICE / 4);
        float4 v = *(const float4*)&h[(base + n) * H + fofs + f4 * 4];
        ((float4*)sm)[n * (SLICE / 4) + f4] = v;
    }
    __syncthreads();

    for (int n = w; n < NPG; n += 32) {
        unsigned pw = 0;
        if (lane < KNN / 4) {
            int4 v = ((const int4*)&g_nbr[(base + n) * KNN])[lane];
            pw = (unsigned)(v.x - base) | ((unsigned)(v.y - base) << 8)
               | ((unsigned)(v.z - base) << 16) | ((unsigned)(v.w - base) << 24);
        }
        uint64_t sacc = 0;  // packed (0.0f, 0.0f)
#pragma unroll 5
        for (int k4 = 0; k4 < KNN / 4; k4++) {
            unsigned p = __shfl_sync(0xffffffffu, pw, k4);
            uint64_t v0 = Xu[(p & 255u) * 32 + lane];
            uint64_t v1 = Xu[((p >> 8) & 255u) * 32 + lane];
            uint64_t v2 = Xu[((p >> 16) & 255u) * 32 + lane];
            uint64_t v3 = Xu[(p >> 24) * 32 + lane];
            uint64_t t0, t1;
            asm("add.rn.f32x2 %0, %1, %2;" : "=l"(t0) : "l"(v0), "l"(v1));
            asm("add.rn.f32x2 %0, %1, %2;" : "=l"(t1) : "l"(v2), "l"(v3));
            asm("add.rn.f32x2 %0, %0, %1;" : "+l"(t0) : "l"(t1));
            asm("add.rn.f32x2 %0, %0, %1;" : "+l"(sacc) : "l"(t0));
        }
        float sx, sy;
        asm("mov.b64 {%0, %1}, %2;" : "=f"(sx), "=f"(sy) : "l"(sacc));
        float2 o; o.x = 0.01f * sx; o.y = 0.01f * sy;
        uint64_t ov; asm("mov.b64 %0, {%1, %2};" : "=l"(ov) : "f"(o.x), "f"(o.y));
        A1u[n * 32 + lane] = ov;
        *(float2*)&a1g[(base + n) * H + fofs + 2 * lane] = o;
    }
    __syncthreads();

    for (int n = w; n < NPG; n += 32) {
        unsigned pw = 0;
        if (lane < KNN / 4) {
            int4 v = ((const int4*)&g_nbr[(base + n) * KNN])[lane];
            pw = (unsigned)(v.x - base) | ((unsigned)(v.y - base) << 8)
               | ((unsigned)(v.z - base) << 16) | ((unsigned)(v.w - base) << 24);
        }
        uint64_t sacc = 0;
#pragma unroll 5
        for (int k4 = 0; k4 < KNN / 4; k4++) {
            unsigned p = __shfl_sync(0xffffffffu, pw, k4);
            uint64_t v0 = A1u[(p & 255u) * 32 + lane];
            uint64_t v1 = A1u[((p >> 8) & 255u) * 32 + lane];
            uint64_t v2 = A1u[((p >> 16) & 255u) * 32 + lane];
            uint64_t v3 = A1u[(p >> 24) * 32 + lane];
            uint64_t t0, t1;
            asm("add.rn.f32x2 %0, %1, %2;" : "=l"(t0) : "l"(v0), "l"(v1));
            asm("add.rn.f32x2 %0, %1, %2;" : "=l"(t1) : "l"(v2), "l"(v3));
            asm("add.rn.f32x2 %0, %0, %1;" : "+l"(t0) : "l"(t1));
            asm("add.rn.f32x2 %0, %0, %1;" : "+l"(sacc) : "l"(t0));
        }
        float sx, sy;
        asm("mov.b64 {%0, %1}, %2;" : "=f"(sx), "=f"(sy) : "l"(sacc));
        float2 o; o.x = 0.01f * sx; o.y = 0.01f * sy;
        *(float2*)&a2g[(base + n) * H + fofs + 2 * lane] = o;
    }
}

// ---------------- 3a. TAGConv combine F=5 -----------------------------------
template <int F, int NPB>
__global__ void tag_kernel(const float* __restrict__ x0, const float* __restrict__ a1,
                           const float* __restrict__ a2, const float* __restrict__ W,
                           const float* __restrict__ bias, float* __restrict__ out) {
    __shared__ float s0[NPB * F], s1[NPB * F], s2[NPB * F];
    int n0 = blockIdx.x * NPB;
    int t = threadIdx.x;  // output channel

    for (int e = t; e < NPB * F; e += 128) {
        s0[e] = x0[n0 * F + e];
        s1[e] = a1[n0 * F + e];
        s2[e] = a2[n0 * F + e];
    }
    __syncthreads();

    float acc[NPB];
#pragma unroll
    for (int n = 0; n < NPB; n++) acc[n] = bias[t];

    for (int j = 0; j < F; j++) {
        float w0 = W[(0 * F + j) * H + t];
        float w1 = W[(1 * F + j) * H + t];
        float w2 = W[(2 * F + j) * H + t];
#pragma unroll
        for (int n = 0; n < NPB; n++)
            acc[n] += s0[n * F + j] * w0 + s1[n * F + j] * w1 + s2[n * F + j] * w2;
    }
#pragma unroll
    for (int n = 0; n < NPB; n++)
        out[(n0 + n) * H + t] = leaky(acc[n]);
}

// ---------------- 3b. TAGConv combine F=128, packed f32x2 + LDS.128 ---------
__global__ __launch_bounds__(128) void tagh_kernel(
    const float* __restrict__ x0, const float* __restrict__ a1,
    const float* __restrict__ a2, const float* __restrict__ W,
    const float* __restrict__ bias, float* __restrict__ out) {
    extern __shared__ __align__(16) float sp[];  // 3 * H * TAG_STRIDE floats
    int n0 = blockIdx.x * TAG_NPB;
    int t = threadIdx.x;

    {
        const float* srcs[3] = {x0 + n0 * H, a1 + n0 * H, a2 + n0 * H};
#pragma unroll
        for (int kk = 0; kk < 3; kk++) {
            float* dst = sp + kk * H * TAG_STRIDE;
            const float* src = srcs[kk];
            for (int e = t; e < TAG_NPB * H; e += 128) {
                int n = e >> 7, j = e & 127;
                dst[j * TAG_STRIDE + n] = src[e];  // transposed: [j][node]
            }
        }
    }
    __syncthreads();

    float bs = bias[t];
    uint64_t acc[TAG_NPB / 2];
    uint64_t bp;
    asm("mov.b64 %0, {%1, %1};" : "=l"(bp) : "f"(bs));
#pragma unroll
    for (int p = 0; p < TAG_NPB / 2; p++) acc[p] = bp;

    const float* sp0 = sp;
    const float* sp1 = sp + H * TAG_STRIDE;
    const float* sp2 = sp + 2 * H * TAG_STRIDE;
    for (int j = 0; j < H; j++) {
        float w0 = W[j * H + t];
        float w1 = W[(H + j) * H + t];
        float w2 = W[(2 * H + j) * H + t];
        uint64_t w0p, w1p, w2p;
        asm("mov.b64 %0, {%1, %1};" : "=l"(w0p) : "f"(w0));
        asm("mov.b64 %0, {%1, %1};" : "=l"(w1p) : "f"(w1));
        asm("mov.b64 %0, {%1, %1};" : "=l"(w2p) : "f"(w2));
        const ulonglong2* v0 = (const ulonglong2*)(sp0 + j * TAG_STRIDE);
        const ulonglong2* v1 = (const ulonglong2*)(sp1 + j * TAG_STRIDE);
        const ulonglong2* v2 = (const ulonglong2*)(sp2 + j * TAG_STRIDE);
#pragma unroll
        for (int q = 0; q < TAG_NPB / 4; q++) {
            ulonglong2 a0 = v0[q];
            ulonglong2 a1v = v1[q];
            ulonglong2 a2v = v2[q];
            asm("fma.rn.f32x2 %0, %1, %2, %0;" : "+l"(acc[2 * q])     : "l"(a0.x),  "l"(w0p));
            asm("fma.rn.f32x2 %0, %1, %2, %0;" : "+l"(acc[2 * q + 1]) : "l"(a0.y),  "l"(w0p));
            asm("fma.rn.f32x2 %0, %1, %2, %0;" : "+l"(acc[2 * q])     : "l"(a1v.x), "l"(w1p));
            asm("fma.rn.f32x2 %0, %1, %2, %0;" : "+l"(acc[2 * q + 1]) : "l"(a1v.y), "l"(w1p));
            asm("fma.rn.f32x2 %0, %1, %2, %0;" : "+l"(acc[2 * q])     : "l"(a2v.x), "l"(w2p));
            asm("fma.rn.f32x2 %0, %1, %2, %0;" : "+l"(acc[2 * q + 1]) : "l"(a2v.y), "l"(w2p));
        }
    }
#pragma unroll
    for (int p = 0; p < TAG_NPB / 2; p++) {
        float lo, hi;
        asm("mov.b64 {%0, %1}, %2;" : "=f"(lo), "=f"(hi) : "l"(acc[p]));
        out[(n0 + 2 * p) * H + t]     = leaky(lo);
        out[(n0 + 2 * p + 1) * H + t] = leaky(hi);
    }
}

// ---------------- 4. mean+max pool per graph (1024 threads) -----------------
__global__ void pool_kernel(const float* __restrict__ h, int col, float* __restrict__ G) {
    int b = blockIdx.x;
    int f = threadIdx.x & 127;        // feature
    int strip = threadIdx.x >> 7;     // 0..7
    float s = 0.0f, m = -1e30f;
    for (int n = strip; n < NPG; n += 8) {
        float v = h[(b * NPG + n) * H + f];
        s += v;
        m = fmaxf(m, v);
    }
    __shared__ float ssum[1024], smax[1024];
    ssum[threadIdx.x] = s;
    smax[threadIdx.x] = m;
    __syncthreads();
    if (strip == 0) {
#pragma unroll
        for (int o = 1; o < 8; o++) {
            s += ssum[o * 128 + f];
            m = fmaxf(m, smax[o * 128 + f]);
        }
        G[b * H2 + col + f]     = s * (1.0f / NPG);
        G[b * H2 + col + H + f] = m;
    }
}

// ---------------- 5. batchnorm over batch dim -------------------------------
__global__ void bn_kernel(float* __restrict__ G, const float* __restrict__ gamma,
                          const float* __restrict__ beta) {
    int c = blockIdx.x * blockDim.x + threadIdx.x;
    if (c >= H2) return;
    float s = 0.0f;
    for (int b = 0; b < NGRAPH; b++) s += G[b * H2 + c];
    float mu = s * (1.0f / NGRAPH);
    float v = 0.0f;
    for (int b = 0; b < NGRAPH; b++) { float d = G[b * H2 + c] - mu; v += d * d; }
    v *= (1.0f / NGRAPH);
    float sc = rsqrtf(v + 1e-5f) * gamma[c];
    float bt = beta[c];
    for (int b = 0; b < NGRAPH; b++)
        G[b * H2 + c] = (G[b * H2 + c] - mu) * sc + bt;
}

// ---------------- 6. dense 768x768 + leaky: 192 blk x 1024 thr, split-K x8 --
__global__ __launch_bounds__(1024) void dense_kernel(
    const float* __restrict__ in, const float* __restrict__ W,
    const float* __restrict__ bias, float* __restrict__ out) {
    __shared__ float s[DRPB * H2];                 // 6 KB
    __shared__ float red[(DQ - 1) * DRPB * 128];   // 7 KB
    int lane = threadIdx.x & 127;
    int q = threadIdx.x >> 7;               // 0..7 = k-segment
    int colblk = blockIdx.x % (H2 / 128);   // 0..5
    int rowblk = blockIdx.x / (H2 / 128);   // 0..31
    int col = colblk * 128 + lane;
    int r0 = rowblk * DRPB;

    for (int e = threadIdx.x; e < DRPB * H2; e += 1024) s[e] = in[r0 * H2 + e];
    __syncthreads();

    const int seg = H2 / DQ;                // 96
    int j0 = q * seg;
    int jend = j0 + seg;

    float a0 = 0.0f, a1 = 0.0f;
    float w0 = W[(j0 + 0) * H2 + col];
    float w1 = W[(j0 + 1) * H2 + col];
    float w2 = W[(j0 + 2) * H2 + col];
    float w3 = W[(j0 + 3) * H2 + col];
    for (int j = j0; j < jend; j += 4) {
        float nw0 = 0.0f, nw1 = 0.0f, nw2 = 0.0f, nw3 = 0.0f;
        if (j + 4 < jend) {                 // predicated preload of next group
            nw0 = W[(j + 4) * H2 + col];
            nw1 = W[(j + 5) * H2 + col];
            nw2 = W[(j + 6) * H2 + col];
            nw3 = W[(j + 7) * H2 + col];
        }
        a0 += s[j + 0] * w0; a1 += s[H2 + j + 0] * w0;
        a0 += s[j + 1] * w1; a1 += s[H2 + j + 1] * w1;
        a0 += s[j + 2] * w2; a1 += s[H2 + j + 2] * w2;
        a0 += s[j + 3] * w3; a1 += s[H2 + j + 3] * w3;
        w0 = nw0; w1 = nw1; w2 = nw2; w3 = nw3;
    }
    if (q) {
        red[((q - 1) * DRPB + 0) * 128 + lane] = a0;
        red[((q - 1) * DRPB + 1) * 128 + lane] = a1;
    }
    __syncthreads();
    if (!q) {
        float bs = bias[col];
#pragma unroll
        for (int seg7 = 0; seg7 < DQ - 1; seg7++) {
            a0 += red[(seg7 * DRPB + 0) * 128 + lane];
            a1 += red[(seg7 * DRPB + 1) * 128 + lane];
        }
        out[(r0 + 0) * H2 + col] = leaky(a0 + bs);
        out[(r0 + 1) * H2 + col] = leaky(a1 + bs);
    }
}

// ---------------- 7. output projection 768 -> 1 -----------------------------
__global__ void final_kernel(const float* __restrict__ G, const float* __restrict__ w,
                             const float* __restrict__ b, float* __restrict__ out) {
    int row = blockIdx.x, t = threadIdx.x;
    float s = 0.0f;
    for (int j = t; j < H2; j += 128) s += G[row * H2 + j] * w[j];
    __shared__ float red[128];
    red[t] = s;
    __syncthreads();
    for (int o = 64; o > 0; o >>= 1) {
        if (t < o) red[t] += red[t + o];
        __syncthreads();
    }
    if (t == 0) out[row] = red[0] + b[0];
}

// ---------------- host launcher ---------------------------------------------
extern "C" void kernel_launch(void* const* d_in, const int* in_sizes, int n_in,
                              void* d_out, int out_size) {
    const float* x       = (const float*)d_in[0];
    const float* conv1_w = (const float*)d_in[2];
    const float* conv1_b = (const float*)d_in[3];
    const float* conv2_w = (const float*)d_in[4];
    const float* conv2_b = (const float*)d_in[5];
    const float* conv3_w = (const float*)d_in[6];
    const float* conv3_b = (const float*)d_in[7];
    const float* bn_g    = (const float*)d_in[8];
    const float* bn_b    = (const float*)d_in[9];
    const float* lin_w   = (const float*)d_in[10];
    const float* lin_b   = (const float*)d_in[11];
    const float* out_w   = (const float*)d_in[12];
    const float* out_b   = (const float*)d_in[13];
    float* out = (float*)d_out;

    float *a1, *a2, *hA, *hB, *t1, *t2, *G, *G2;
    cudaGetSymbolAddress((void**)&a1, g_a1);
    cudaGetSymbolAddress((void**)&a2, g_a2);
    cudaGetSymbolAddress((void**)&hA, g_hA);
    cudaGetSymbolAddress((void**)&hB, g_hB);
    cudaGetSymbolAddress((void**)&t1, g_t1);
    cudaGetSymbolAddress((void**)&t2, g_t2);
    cudaGetSymbolAddress((void**)&G,  g_G);
    cudaGetSymbolAddress((void**)&G2, g_G2);

    const int smemFin = NPG * 101 * 4 + 2 * NPG * FIN * 4;      // 113664
    const int smemH   = 2 * NPG * SLICE * 4;                    // 131072
    const int smemTag = 3 * H * TAG_STRIDE * 4;                 // 55296
    cudaFuncSetAttribute(agg2_fin_kernel, cudaFuncAttributeMaxDynamicSharedMemorySize, smemFin);
    cudaFuncSetAttribute(agg2_h_kernel,   cudaFuncAttributeMaxDynamicSharedMemorySize, smemH);
    cudaFuncSetAttribute(tagh_kernel,     cudaFuncAttributeMaxDynamicSharedMemorySize, smemTag);

    const int dgrid = (H2 / 128) * (NGRAPH / DRPB);   // 6 * 32 = 192

    // launch index:                                                          //
    knn_kernel<<<NNODE, 256>>>(x);                                            // 0
    agg2_fin_kernel<<<NGRAPH, 256, smemFin>>>(x, a1, a2);                     // 1
    tag_kernel<FIN, 32><<<NNODE / 32, 128>>>(x, a1, a2, conv1_w, conv1_b, hA);// 2
    agg2_h_kernel<<<NGRAPH * 2, 1024, smemH>>>(hA, t1, t2);                   // 3 <- profiled (control ~65.7us)
    pool_kernel<<<NGRAPH, 1024>>>(hA, 0, G);                                  // 4
    tagh_kernel<<<NNODE / TAG_NPB, 128, smemTag>>>(hA, t1, t2, conv2_w, conv2_b, hB); // 5
    agg2_h_kernel<<<NGRAPH * 2, 1024, smemH>>>(hB, t1, t2);                   // 6
    pool_kernel<<<NGRAPH, 1024>>>(hB, 2 * H, G);                              // 7
    tagh_kernel<<<NNODE / TAG_NPB, 128, smemTag>>>(hB, t1, t2, conv3_w, conv3_b, hA); // 8
    pool_kernel<<<NGRAPH, 1024>>>(hA, 4 * H, G);                              // 9

    bn_kernel<<<6, 128>>>(G, bn_g, bn_b);

    dense_kernel<<<dgrid, 1024>>>(G,  lin_w + 0 * H2 * H2, lin_b + 0 * H2, G2);
    dense_kernel<<<dgrid, 1024>>>(G2, lin_w + 1 * H2 * H2, lin_b + 1 * H2, G);
    dense_kernel<<<dgrid, 1024>>>(G,  lin_w + 2 * H2 * H2, lin_b + 2 * H2, G2);
    dense_kernel<<<dgrid, 1024>>>(G2, lin_w + 3 * H2 * H2, lin_b + 3 * H2, G);
    dense_kernel<<<dgrid, 1024>>>(G,  lin_w + 4 * H2 * H2, lin_b + 4 * H2, G2);

    final_kernel<<<NGRAPH, 128>>>(G2, out_w, out_b, out);
}